// round 4
// baseline (speedup 1.0000x reference)
#include <cuda_runtime.h>

#define N_NODES 50000
#define D 128

// Scratch (alloc-free rule: __device__ globals)
__device__ float g_sum[(size_t)N_NODES * D];   // segment sums
__device__ float g_deg[N_NODES];               // degree (float counts)
__device__ float g_h[(size_t)N_NODES * D];     // layer-1 activations

// ---------------------------------------------------------------------------
// Zero scratch. do_deg!=0 also zeroes deg.
// ---------------------------------------------------------------------------
__global__ void zero_kernel(int do_deg) {
    int i = blockIdx.x * blockDim.x + threadIdx.x;
    int n = N_NODES * D;
    if (i < n) g_sum[i] = 0.0f;
    if (do_deg && i < N_NODES) g_deg[i] = 0.0f;
}

// ---------------------------------------------------------------------------
// Scatter: one warp per edge. Lane l handles features [4l, 4l+4).
// Gather is a coalesced 512B read per edge; scatter is a red.global.add.v4.f32
// (vector reduction, sm_90+) -> 32 reductions per edge instead of 128.
// use_h!=0 gathers from g_h (layer 2) instead of the feat pointer.
// edge_index is int32 (JAX x64-disabled demotes int64 -> int32).
// ---------------------------------------------------------------------------
__global__ void scatter_kernel(const float* __restrict__ feat,
                               const int* __restrict__ src,
                               const int* __restrict__ dst,
                               int E, int do_deg, int use_h) {
    int warp = (blockIdx.x * blockDim.x + threadIdx.x) >> 5;
    int lane = threadIdx.x & 31;
    if (warp >= E) return;
    int s = src[warp];   // broadcast load within warp
    int d = dst[warp];
    if ((unsigned)s >= N_NODES || (unsigned)d >= N_NODES) return;  // safety

    const float* fp = use_h ? g_h : feat;
    float4 v = ((const float4*)(fp + (size_t)s * D))[lane];
    float4* addr = ((float4*)(g_sum + (size_t)d * D)) + lane;
    asm volatile("red.global.add.v4.f32 [%0], {%1,%2,%3,%4};"
                 :: "l"(addr), "f"(v.x), "f"(v.y), "f"(v.z), "f"(v.w)
                 : "memory");
    if (do_deg && lane == 0) {
        asm volatile("red.global.add.f32 [%0], %1;"
                     :: "l"(g_deg + d), "f"(1.0f) : "memory");
    }
}

// ---------------------------------------------------------------------------
// Fused SAGE linear:  out = (g_sum/max(deg,1)) @ Wl + bl + xin @ Wr  (+ReLU)
// Implemented as A[50000x256] @ B[256x128] with A = [agg | xin], B = [Wl; Wr].
// Tile: BM=64, BN=128, BK=32. 256 threads, each computes 8x4 outputs.
// use_h!=0: the "self" features xin come from g_h (layer 2).
// to_h !=0: write the result into g_h (layer 1) instead of out.
// ---------------------------------------------------------------------------
__global__ void sage_gemm(const float* __restrict__ xin,
                          const float* __restrict__ Wl,
                          const float* __restrict__ bl,
                          const float* __restrict__ Wr,
                          float* __restrict__ out,
                          int relu, int use_h, int to_h) {
    __shared__ float As[64][33];
    __shared__ float Bs[32][128];
    __shared__ float sinv[64];

    int tid  = threadIdx.x;          // 0..255
    int row0 = blockIdx.x * 64;

    const float* self = use_h ? g_h : xin;
    float* dstp = to_h ? g_h : out;

    if (tid < 64) {
        int r = row0 + tid;
        float dg = (r < N_NODES) ? g_deg[r] : 1.0f;
        sinv[tid] = 1.0f / fmaxf(dg, 1.0f);
    }
    __syncthreads();

    int rg = tid >> 5;   // 0..7  row group (8 rows each)
    int cg = tid & 31;   // 0..31 col group (cols cg, cg+32, cg+64, cg+96)

    float acc[8][4];
#pragma unroll
    for (int r = 0; r < 8; r++)
#pragma unroll
        for (int c = 0; c < 4; c++) acc[r][c] = 0.0f;

    for (int kc = 0; kc < 256; kc += 32) {
        // ---- load A tile: 64 rows x 32 k. Each thread: 8 consecutive k of one row.
        {
            int idx = tid * 8;
            int r   = idx >> 5;        // tile row 0..63
            int k0  = idx & 31;        // 0,8,16,24
            int grow = row0 + r;
            int kg   = kc + k0;        // chunk never straddles the 128 boundary
            float v[8];
            if (grow < N_NODES) {
                const float* p;
                float scale;
                if (kg < 128) { p = g_sum + (size_t)grow * D + kg;         scale = sinv[r]; }
                else          { p = self  + (size_t)grow * D + (kg - 128); scale = 1.0f;   }
                float4 p0 = ((const float4*)p)[0];
                float4 p1 = ((const float4*)p)[1];
                v[0] = p0.x * scale; v[1] = p0.y * scale;
                v[2] = p0.z * scale; v[3] = p0.w * scale;
                v[4] = p1.x * scale; v[5] = p1.y * scale;
                v[6] = p1.z * scale; v[7] = p1.w * scale;
            } else {
#pragma unroll
                for (int i = 0; i < 8; i++) v[i] = 0.0f;
            }
#pragma unroll
            for (int i = 0; i < 8; i++) As[r][k0 + i] = v[i];
        }
        // ---- load B tile: 32 k x 128 cols. Each thread: 16 consecutive cols of one k.
        {
            int idx = tid * 16;
            int kk  = idx >> 7;        // 0..31
            int c0  = idx & 127;       // multiples of 16
            int kg  = kc + kk;
            const float* p = (kg < 128) ? (Wl + (size_t)kg * D + c0)
                                        : (Wr + (size_t)(kg - 128) * D + c0);
            float4 q0 = ((const float4*)p)[0];
            float4 q1 = ((const float4*)p)[1];
            float4 q2 = ((const float4*)p)[2];
            float4 q3 = ((const float4*)p)[3];
            float* bp = &Bs[kk][c0];
            bp[0]=q0.x; bp[1]=q0.y; bp[2]=q0.z; bp[3]=q0.w;
            bp[4]=q1.x; bp[5]=q1.y; bp[6]=q1.z; bp[7]=q1.w;
            bp[8]=q2.x; bp[9]=q2.y; bp[10]=q2.z; bp[11]=q2.w;
            bp[12]=q3.x; bp[13]=q3.y; bp[14]=q3.z; bp[15]=q3.w;
        }
        __syncthreads();

#pragma unroll
        for (int kk = 0; kk < 32; kk++) {
            float b0 = Bs[kk][cg];
            float b1 = Bs[kk][32 + cg];
            float b2 = Bs[kk][64 + cg];
            float b3 = Bs[kk][96 + cg];
#pragma unroll
            for (int r = 0; r < 8; r++) {
                float a = As[rg * 8 + r][kk];
                acc[r][0] = fmaf(a, b0, acc[r][0]);
                acc[r][1] = fmaf(a, b1, acc[r][1]);
                acc[r][2] = fmaf(a, b2, acc[r][2]);
                acc[r][3] = fmaf(a, b3, acc[r][3]);
            }
        }
        __syncthreads();
    }

    // ---- epilogue: bias (+ReLU), coalesced store
#pragma unroll
    for (int r = 0; r < 8; r++) {
        int grow = row0 + rg * 8 + r;
        if (grow >= N_NODES) continue;
#pragma unroll
        for (int c = 0; c < 4; c++) {
            int col = c * 32 + cg;
            float v = acc[r][c] + bl[col];
            if (relu) v = fmaxf(v, 0.0f);
            dstp[(size_t)grow * D + col] = v;
        }
    }
}

// ---------------------------------------------------------------------------
extern "C" void kernel_launch(void* const* d_in, const int* in_sizes, int n_in,
                              void* d_out, int out_size) {
    const float* x   = (const float*)d_in[0];
    const int*   ei  = (const int*)d_in[1];     // int32: JAX demotes int64
    const float* W1l = (const float*)d_in[2];
    const float* b1l = (const float*)d_in[3];
    const float* W1r = (const float*)d_in[4];
    const float* W2l = (const float*)d_in[5];
    const float* b2l = (const float*)d_in[6];
    const float* W2r = (const float*)d_in[7];
    float* out = (float*)d_out;

    int E = in_sizes[1] / 2;
    const int* src = ei;
    const int* dst = ei + E;

    int zgrid = (N_NODES * D + 255) / 256;
    int sgrid = (E + 7) / 8;            // 8 warps (edges) per 256-thread block
    int ggrid = (N_NODES + 63) / 64;

    // Layer 1: agg from x, self x, write h (ReLU)
    zero_kernel<<<zgrid, 256>>>(1);
    scatter_kernel<<<sgrid, 256>>>(x, src, dst, E, 1, 0);
    sage_gemm<<<ggrid, 256>>>(x, W1l, b1l, W1r, nullptr, 1, 0, 1);
    // Layer 2: agg from h, self h, write out (deg reused)
    zero_kernel<<<zgrid, 256>>>(0);
    scatter_kernel<<<sgrid, 256>>>(nullptr, src, dst, E, 0, 1);
    sage_gemm<<<ggrid, 256>>>(nullptr, W2l, b2l, W2r, out, 0, 1, 0);
}

// round 6
// speedup vs baseline: 1.1472x; 1.1472x over previous
#include <cuda_runtime.h>

#define N_NODES 50000
#define D 128

// Scratch (alloc-free rule: __device__ globals)
__device__ float g_sum[(size_t)N_NODES * D];   // segment sums
__device__ float g_deg[N_NODES];               // degree (float counts)
__device__ float g_h[(size_t)N_NODES * D];     // layer-1 activations

// ---------------------------------------------------------------------------
// Vectorized zero of g_sum (+ g_deg). 1.6M float4 stores.
// ---------------------------------------------------------------------------
__global__ void zero_kernel(int do_deg) {
    int i = blockIdx.x * blockDim.x + threadIdx.x;
    const int n4 = N_NODES * D / 4;          // 1,600,000
    float4 z = make_float4(0.f, 0.f, 0.f, 0.f);
    if (i < n4) ((float4*)g_sum)[i] = z;
    if (do_deg && i < N_NODES / 4) ((float4*)g_deg)[i] = z;  // 50000 % 4 == 0
}

// ---------------------------------------------------------------------------
// Scatter: one warp per edge. Lane l handles features [4l, 4l+4).
// Gather: coalesced 512B read; scatter: red.global.add.v4.f32 (32 reds/edge).
// use_h!=0 gathers from g_h (layer 2). edge_index is int32.
// ---------------------------------------------------------------------------
__global__ void scatter_kernel(const float* __restrict__ feat,
                               const int* __restrict__ src,
                               const int* __restrict__ dst,
                               int E, int do_deg, int use_h) {
    int warp = (blockIdx.x * blockDim.x + threadIdx.x) >> 5;
    int lane = threadIdx.x & 31;
    if (warp >= E) return;
    int s = __ldg(src + warp);
    int d = __ldg(dst + warp);
    if ((unsigned)s >= N_NODES || (unsigned)d >= N_NODES) return;  // safety

    const float* fp = use_h ? g_h : feat;
    float4 v = ((const float4*)(fp + (size_t)s * D))[lane];
    float4* addr = ((float4*)(g_sum + (size_t)d * D)) + lane;
    asm volatile("red.global.add.v4.f32 [%0], {%1,%2,%3,%4};"
                 :: "l"(addr), "f"(v.x), "f"(v.y), "f"(v.z), "f"(v.w)
                 : "memory");
    if (do_deg && lane == 0) {
        asm volatile("red.global.add.f32 [%0], %1;"
                     :: "l"(g_deg + d), "f"(1.0f) : "memory");
    }
}

// ---------------------------------------------------------------------------
// Fused SAGE linear:  out = (g_sum/max(deg,1)) @ Wl + bl + self @ Wr  (+ReLU)
// A[50000x256] @ B[256x128], A = [agg | self], B = [Wl; Wr].
// Classic SGEMM: BM=128, BN=128, BK=16; 256 threads (16x16), 8x8 micro-tile,
// float4 shared loads on both operands (4 LDS.128 : 64 FMA).
// use_h: self = g_h.  to_h: write g_h AND re-zero this block's g_sum rows.
// ---------------------------------------------------------------------------
__global__ __launch_bounds__(256) void sage_gemm(
        const float* __restrict__ xin,
        const float* __restrict__ Wl,
        const float* __restrict__ bl,
        const float* __restrict__ Wr,
        float* __restrict__ out,
        int relu, int use_h, int to_h) {
    __shared__ float As[16][132];   // transposed A tile, padded
    __shared__ float Bs[16][132];   // B tile, padded
    __shared__ float sinv[128];

    const int tid  = threadIdx.x;        // 0..255
    const int tx   = tid & 15;           // micro-tile col group
    const int ty   = tid >> 4;           // micro-tile row group
    const int row0 = blockIdx.x * 128;

    const float* self = use_h ? g_h : xin;
    float* dstp = to_h ? g_h : out;

    if (tid < 128) {
        int r = row0 + tid;
        float dg = (r < N_NODES) ? g_deg[r] : 1.0f;
        sinv[tid] = 1.0f / fmaxf(dg, 1.0f);
    }
    __syncthreads();

    float acc[8][8];
#pragma unroll
    for (int i = 0; i < 8; i++)
#pragma unroll
        for (int j = 0; j < 8; j++) acc[i][j] = 0.0f;

    for (int kc = 0; kc < 256; kc += 16) {
        // ---- A tile: 128 rows x 16 k, stored transposed As[k][row].
        // 512 float4 loads; each thread 2. f -> row r = f>>2, k-quad kq = (f&3)*4.
#pragma unroll
        for (int i = 0; i < 2; i++) {
            int f  = tid * 2 + i;
            int r  = f >> 2;
            int kq = (f & 3) * 4;
            int grow = row0 + r;
            int kg   = kc + kq;          // 16-chunk never straddles k=128
            float4 v = make_float4(0.f, 0.f, 0.f, 0.f);
            if (grow < N_NODES) {
                if (kg < 128) {
                    v = *(const float4*)(g_sum + (size_t)grow * D + kg);
                    float sc = sinv[r];
                    v.x *= sc; v.y *= sc; v.z *= sc; v.w *= sc;
                } else {
                    v = *(const float4*)(self + (size_t)grow * D + (kg - 128));
                }
            }
            As[kq + 0][r] = v.x;
            As[kq + 1][r] = v.y;
            As[kq + 2][r] = v.z;
            As[kq + 3][r] = v.w;
        }
        // ---- B tile: 16 k x 128 cols. f -> k = f>>5, col c4 = (f&31)*4.
#pragma unroll
        for (int i = 0; i < 2; i++) {
            int f  = tid * 2 + i;
            int kk = f >> 5;
            int c4 = (f & 31) * 4;
            int kg = kc + kk;
            const float* p = (kg < 128) ? (Wl + (size_t)kg * D + c4)
                                        : (Wr + (size_t)(kg - 128) * D + c4);
            float4 v = *(const float4*)p;
            *(float4*)&Bs[kk][c4] = v;
        }
        __syncthreads();

#pragma unroll
        for (int kk = 0; kk < 16; kk++) {
            float4 a0 = *(float4*)&As[kk][ty * 4];
            float4 a1 = *(float4*)&As[kk][64 + ty * 4];
            float4 b0 = *(float4*)&Bs[kk][tx * 4];
            float4 b1 = *(float4*)&Bs[kk][64 + tx * 4];
            float a[8] = {a0.x, a0.y, a0.z, a0.w, a1.x, a1.y, a1.z, a1.w};
            float b[8] = {b0.x, b0.y, b0.z, b0.w, b1.x, b1.y, b1.z, b1.w};
#pragma unroll
            for (int i = 0; i < 8; i++)
#pragma unroll
                for (int j = 0; j < 8; j++)
                    acc[i][j] = fmaf(a[i], b[j], acc[i][j]);
        }
        __syncthreads();
    }

    // ---- epilogue: bias (+ReLU), vectorized stores
    float bv[8];
#pragma unroll
    for (int j = 0; j < 4; j++) bv[j]     = __ldg(bl + tx * 4 + j);
#pragma unroll
    for (int j = 0; j < 4; j++) bv[4 + j] = __ldg(bl + 64 + tx * 4 + j);

#pragma unroll
    for (int i = 0; i < 8; i++) {
        int r    = (i < 4) ? (ty * 4 + i) : (64 + ty * 4 + (i - 4));
        int grow = row0 + r;
        if (grow >= N_NODES) continue;
        float4 o0, o1;
        o0.x = acc[i][0] + bv[0]; o0.y = acc[i][1] + bv[1];
        o0.z = acc[i][2] + bv[2]; o0.w = acc[i][3] + bv[3];
        o1.x = acc[i][4] + bv[4]; o1.y = acc[i][5] + bv[5];
        o1.z = acc[i][6] + bv[6]; o1.w = acc[i][7] + bv[7];
        if (relu) {
            o0.x = fmaxf(o0.x, 0.f); o0.y = fmaxf(o0.y, 0.f);
            o0.z = fmaxf(o0.z, 0.f); o0.w = fmaxf(o0.w, 0.f);
            o1.x = fmaxf(o1.x, 0.f); o1.y = fmaxf(o1.y, 0.f);
            o1.z = fmaxf(o1.z, 0.f); o1.w = fmaxf(o1.w, 0.f);
        }
        *(float4*)(dstp + (size_t)grow * D + tx * 4)      = o0;
        *(float4*)(dstp + (size_t)grow * D + 64 + tx * 4) = o1;
    }

    // ---- fused re-zero of this block's g_sum rows (layer 1 only).
    // All reads of these rows by this block happened in the k-loop above;
    // no other block touches them.
    if (to_h) {
        float4 z = make_float4(0.f, 0.f, 0.f, 0.f);
        // 128 rows x 128 cols = 4096 float4; 16 per thread.
        float4* base = (float4*)(g_sum + (size_t)row0 * D);
        int maxq = (N_NODES - row0 < 128 ? N_NODES - row0 : 128) * (D / 4);
#pragma unroll
        for (int q = 0; q < 16; q++) {
            int idx = q * 256 + tid;
            if (idx < maxq) base[idx] = z;
        }
    }
}

// ---------------------------------------------------------------------------
extern "C" void kernel_launch(void* const* d_in, const int* in_sizes, int n_in,
                              void* d_out, int out_size) {
    const float* x   = (const float*)d_in[0];
    const int*   ei  = (const int*)d_in[1];     // int32 (JAX demotes int64)
    const float* W1l = (const float*)d_in[2];
    const float* b1l = (const float*)d_in[3];
    const float* W1r = (const float*)d_in[4];
    const float* W2l = (const float*)d_in[5];
    const float* b2l = (const float*)d_in[6];
    const float* W2r = (const float*)d_in[7];
    float* out = (float*)d_out;

    int E = in_sizes[1] / 2;
    const int* src = ei;
    const int* dst = ei + E;

    int zgrid = (N_NODES * D / 4 + 255) / 256;
    int sgrid = (E + 7) / 8;                 // 8 warps (edges) per block
    int ggrid = (N_NODES + 127) / 128;       // 391

    // Layer 1: agg from x, self x, write h (ReLU); epilogue re-zeroes g_sum
    zero_kernel<<<zgrid, 256>>>(1);
    scatter_kernel<<<sgrid, 256>>>(x, src, dst, E, 1, 0);
    sage_gemm<<<ggrid, 256>>>(x, W1l, b1l, W1r, nullptr, 1, 0, 1);
    // Layer 2: agg from h, self h, write out (deg reused, g_sum pre-zeroed)
    scatter_kernel<<<sgrid, 256>>>(nullptr, src, dst, E, 0, 1);
    sage_gemm<<<ggrid, 256>>>(nullptr, W2l, b2l, W2r, out, 0, 1, 0);
}